// round 10
// baseline (speedup 1.0000x reference)
#include <cuda_runtime.h>

// GATLayer: B=8, N=1024, INP=7, D=32, H=4
// Identity 1: softmax_j(s_i + s_j + ba) == softmax_j(s_j) => att independent
//   of i => output row constant per batch.
// Identity 2: |s_j| small => no max subtraction needed in fp32 softmax:
//   m[b,h,:] = sum_j e^{s_j[h]} fx[j,:] / sum_j e^{s_j[h]}
//   => aggregation = per-block partials computed inside the MLP kernel.

#define BB 8
#define NN 1024
#define DD 32
#define HH 4

typedef unsigned long long ull;

// packed f32x2 helpers (FFMA2 is PTX-only; ptxas never auto-fuses)
#define PACK2(r, f)  asm("mov.b64 %0, {%1, %1};" : "=l"(r) : "f"(f))
#define FMA2(acc, w, h) \
    asm("fma.rn.f32x2 %0, %1, %2, %3;" : "=l"(acc) : "l"(w), "l"(h), "l"(acc))
#define ADD2(r, a, b) \
    asm("add.rn.f32x2 %0, %1, %2;" : "=l"(r) : "l"(a), "l"(b))
#define UNPK(lo, hi, v) \
    asm("mov.b64 {%0, %1}, %2;" : "=f"(lo), "=f"(hi) : "l"(v))

// per-block partials: [128 blocks][132] = 128 (e*fx, [h][d]) + 4 (e sums)
__device__ float g_part[128 * 132];

static __device__ __forceinline__ float lrelu(float t) {
    return fmaxf(t, 0.2f * t);
}

// ---------------------------------------------------------------------------
// Kernel 1: message MLP + s_j + per-block softmax-numerator partials.
// 128 blocks x 256 threads; 64 nodes/block, 8 threads per NODE PAIR
// (s = t&7, group g = t>>3 owns nodes g and g+32). Stages B/C use packed
// fma.rn.f32x2 (two accumulator columns per op); weight LDS.128 feeds
// 8 FFMA2 (2 nodes x 2 colgroups x 2 pairs). Accumulators are scalars bound
// to fixed column groups (A<->2s+rot, B<->2s+1-rot, rot=s>>2) — no spills.
// sh1/sh2 alias the epilogue transpose via a union (barrier separates uses).
// ---------------------------------------------------------------------------
#define HSTR 68
#define TSTR 65

__global__ __launch_bounds__(256) void k_mlp(
    const float* __restrict__ x,
    const float* __restrict__ W1, const float* __restrict__ b1,
    const float* __restrict__ W2, const float* __restrict__ b2,
    const float* __restrict__ W3, const float* __restrict__ b3,
    const float* __restrict__ Wa)
{
    __shared__ float sW1[7 * 64];
    __shared__ float sW2[64 * 64];
    __shared__ float sW3[64 * 32];
    __shared__ float sWaj[32 * 4];       // Wa rows 32..63, [d][h]
    __shared__ float sb1[64], sb2[64], sb3[32];
    __shared__ float sx[448];            // x for this block's 64 nodes
    __shared__ union UU {
        struct { float sh1[64 * HSTR]; float sh2[64 * HSTR]; } a;  // 8704 f
        struct { float stmp[128 * TSTR + TSTR]; float stz[5 * TSTR]; } r;
    } u;

    const int t = threadIdx.x;

    // ---- stage weights + x ----
    {
        float4* d2 = (float4*)sW2; const float4* s2 = (const float4*)W2;
#pragma unroll
        for (int i = 0; i < 4; i++) d2[t + i * 256] = s2[t + i * 256];
        float4* d3 = (float4*)sW3; const float4* s3 = (const float4*)W3;
#pragma unroll
        for (int i = 0; i < 2; i++) d3[t + i * 256] = s3[t + i * 256];
        if (t < 112) {
            ((float4*)sW1)[t] = ((const float4*)W1)[t];
            ((float4*)sx)[t] = ((const float4*)(x + blockIdx.x * 448))[t];
        }
        else if (t < 144) ((float4*)sWaj)[t - 112] = ((const float4*)(Wa + 128))[t - 112];
        else if (t < 160) ((float4*)sb1)[t - 144] = ((const float4*)b1)[t - 144];
        else if (t < 176) ((float4*)sb2)[t - 160] = ((const float4*)b2)[t - 160];
        else if (t < 184) ((float4*)sb3)[t - 176] = ((const float4*)b3)[t - 176];
    }
    __syncthreads();

    const int g = t >> 3;                // node group 0..31 (nodes g, g+32)
    const int s = t & 7;
    const int rot = s >> 2;              // 0/1
    const int cgA = 2 * s + rot;         // accumulator A's column group
    const int cgB = 2 * s + 1 - rot;     // accumulator B's column group

    // ---- Stage A: layer 1 for both nodes (scalar; only 7 k's) ----
    {
        float xv0[7], xv1[7];
#pragma unroll
        for (int k = 0; k < 7; k++) { xv0[k] = sx[g * 7 + k]; xv1[k] = sx[(g + 32) * 7 + k]; }

        const float4 bA = ((const float4*)sb1)[cgA];
        const float4 bB = ((const float4*)sb1)[cgB];
        float nA0 = bA.x, nA1 = bA.y, nA2 = bA.z, nA3 = bA.w;
        float nB0 = bB.x, nB1 = bB.y, nB2 = bB.z, nB3 = bB.w;
        float mA0 = bA.x, mA1 = bA.y, mA2 = bA.z, mA3 = bA.w;
        float mB0 = bB.x, mB1 = bB.y, mB2 = bB.z, mB3 = bB.w;
#pragma unroll
        for (int k = 0; k < 7; k++) {
            const float xk0 = xv0[k], xk1 = xv1[k];
            const float4* row = (const float4*)(sW1 + k * 64);
            const float4 wA = row[cgA];
            const float4 wB = row[cgB];
            nA0 += xk0 * wA.x; nA1 += xk0 * wA.y; nA2 += xk0 * wA.z; nA3 += xk0 * wA.w;
            nB0 += xk0 * wB.x; nB1 += xk0 * wB.y; nB2 += xk0 * wB.z; nB3 += xk0 * wB.w;
            mA0 += xk1 * wA.x; mA1 += xk1 * wA.y; mA2 += xk1 * wA.z; mA3 += xk1 * wA.w;
            mB0 += xk1 * wB.x; mB1 += xk1 * wB.y; mB2 += xk1 * wB.z; mB3 += xk1 * wB.w;
        }
        float4* o0 = (float4*)(u.a.sh1 + g * HSTR + 8 * s);
        float4* o1 = (float4*)(u.a.sh1 + (g + 32) * HSTR + 8 * s);
        o0[rot]     = make_float4(lrelu(nA0), lrelu(nA1), lrelu(nA2), lrelu(nA3));
        o0[1 - rot] = make_float4(lrelu(nB0), lrelu(nB1), lrelu(nB2), lrelu(nB3));
        o1[rot]     = make_float4(lrelu(mA0), lrelu(mA1), lrelu(mA2), lrelu(mA3));
        o1[1 - rot] = make_float4(lrelu(mB0), lrelu(mB1), lrelu(mB2), lrelu(mB3));
    }
    __syncthreads();

    // ---- Stage B: layer 2 for both nodes, packed f32x2 ----
    {
        ulonglong2 bAp = ((const ulonglong2*)sb2)[cgA];
        ulonglong2 bBp = ((const ulonglong2*)sb2)[cgB];
        ull nA0 = bAp.x, nA1 = bAp.y;    // node0, colgroup A, (d0d1)(d2d3)
        ull nB0 = bBp.x, nB1 = bBp.y;
        ull mA0 = bAp.x, mA1 = bAp.y;    // node1
        ull mB0 = bBp.x, mB1 = bBp.y;
        const float* h1r0 = u.a.sh1 + g * HSTR;
        const float* h1r1 = u.a.sh1 + (g + 32) * HSTR;
#pragma unroll
        for (int k = 0; k < 64; k += 2) {
            const float2 hk0 = *(const float2*)(h1r0 + k);
            const float2 hk1 = *(const float2*)(h1r1 + k);
            ull p00, p01, p10, p11;
            PACK2(p00, hk0.x); PACK2(p01, hk0.y);
            PACK2(p10, hk1.x); PACK2(p11, hk1.y);
            const ulonglong2* row0 = (const ulonglong2*)(sW2 + k * 64);
            const ulonglong2* row1 = (const ulonglong2*)(sW2 + (k + 1) * 64);
            {
                const ulonglong2 wA = row0[cgA];
                const ulonglong2 wB = row0[cgB];
                FMA2(nA0, wA.x, p00); FMA2(nA1, wA.y, p00);
                FMA2(nB0, wB.x, p00); FMA2(nB1, wB.y, p00);
                FMA2(mA0, wA.x, p10); FMA2(mA1, wA.y, p10);
                FMA2(mB0, wB.x, p10); FMA2(mB1, wB.y, p10);
            }
            {
                const ulonglong2 wA = row1[cgA];
                const ulonglong2 wB = row1[cgB];
                FMA2(nA0, wA.x, p01); FMA2(nA1, wA.y, p01);
                FMA2(nB0, wB.x, p01); FMA2(nB1, wB.y, p01);
                FMA2(mA0, wA.x, p11); FMA2(mA1, wA.y, p11);
                FMA2(mB0, wB.x, p11); FMA2(mB1, wB.y, p11);
            }
        }
        float v0, v1, v2, v3, w0, w1, w2, w3;
        float4* o0 = (float4*)(u.a.sh2 + g * HSTR + 8 * s);
        float4* o1 = (float4*)(u.a.sh2 + (g + 32) * HSTR + 8 * s);
        UNPK(v0, v1, nA0); UNPK(v2, v3, nA1);
        UNPK(w0, w1, nB0); UNPK(w2, w3, nB1);
        o0[rot]     = make_float4(lrelu(v0), lrelu(v1), lrelu(v2), lrelu(v3));
        o0[1 - rot] = make_float4(lrelu(w0), lrelu(w1), lrelu(w2), lrelu(w3));
        UNPK(v0, v1, mA0); UNPK(v2, v3, mA1);
        UNPK(w0, w1, mB0); UNPK(w2, w3, mB1);
        o1[rot]     = make_float4(lrelu(v0), lrelu(v1), lrelu(v2), lrelu(v3));
        o1[1 - rot] = make_float4(lrelu(w0), lrelu(w1), lrelu(w2), lrelu(w3));
    }
    __syncthreads();

    // ---- Stage C: layer 3, dims [4s,4s+4) for both nodes, packed f32x2 ----
    float f0, f1, f2, f3;       // node0 fx
    float q0, q1, q2, q3;       // node1 fx
    {
        const ulonglong2 b3p = ((const ulonglong2*)sb3)[s];
        ull ve0 = b3p.x, ve1 = b3p.y;   // node0 even-j chain
        ull vo0 = 0, vo1 = 0;           // node0 odd-j chain (zero = 2x +0.0f)
        ull ue0 = b3p.x, ue1 = b3p.y;   // node1 even
        ull uo0 = 0, uo1 = 0;           // node1 odd
        const float* h2r0 = u.a.sh2 + g * HSTR;
        const float* h2r1 = u.a.sh2 + (g + 32) * HSTR;
#pragma unroll
        for (int j = 0; j < 64; j += 2) {
            const float2 ha = *(const float2*)(h2r0 + j);
            const float2 hb = *(const float2*)(h2r1 + j);
            ull pa0, pa1, pb0, pb1;
            PACK2(pa0, ha.x); PACK2(pa1, ha.y);
            PACK2(pb0, hb.x); PACK2(pb1, hb.y);
            const ulonglong2 w0 = ((const ulonglong2*)sW3)[j * 8 + s];
            const ulonglong2 w1 = ((const ulonglong2*)sW3)[(j + 1) * 8 + s];
            FMA2(ve0, w0.x, pa0); FMA2(ve1, w0.y, pa0);
            FMA2(ue0, w0.x, pb0); FMA2(ue1, w0.y, pb0);
            FMA2(vo0, w1.x, pa1); FMA2(vo1, w1.y, pa1);
            FMA2(uo0, w1.x, pb1); FMA2(uo1, w1.y, pb1);
        }
        ull r0, r1;
        ADD2(r0, ve0, vo0); ADD2(r1, ve1, vo1);
        UNPK(f0, f1, r0); UNPK(f2, f3, r1);
        ADD2(r0, ue0, uo0); ADD2(r1, ue1, uo1);
        UNPK(q0, q1, r0); UNPK(q2, q3, r1);
    }

    // ---- s_j = fx @ Wa[D:]: partials over lane's 4 dims, 8-lane all-reduce
    float sj0, sj1, sj2, sj3;   // node0
    float tj0, tj1, tj2, tj3;   // node1
    {
        const float4 w0 = ((const float4*)sWaj)[4 * s + 0];
        const float4 w1 = ((const float4*)sWaj)[4 * s + 1];
        const float4 w2 = ((const float4*)sWaj)[4 * s + 2];
        const float4 w3 = ((const float4*)sWaj)[4 * s + 3];
        sj0 = f0 * w0.x + f1 * w1.x + f2 * w2.x + f3 * w3.x;
        sj1 = f0 * w0.y + f1 * w1.y + f2 * w2.y + f3 * w3.y;
        sj2 = f0 * w0.z + f1 * w1.z + f2 * w2.z + f3 * w3.z;
        sj3 = f0 * w0.w + f1 * w1.w + f2 * w2.w + f3 * w3.w;
        tj0 = q0 * w0.x + q1 * w1.x + q2 * w2.x + q3 * w3.x;
        tj1 = q0 * w0.y + q1 * w1.y + q2 * w2.y + q3 * w3.y;
        tj2 = q0 * w0.z + q1 * w1.z + q2 * w2.z + q3 * w3.z;
        tj3 = q0 * w0.w + q1 * w1.w + q2 * w2.w + q3 * w3.w;
    }
#pragma unroll
    for (int o = 1; o < 8; o <<= 1) {
        sj0 += __shfl_xor_sync(0xffffffffu, sj0, o);
        sj1 += __shfl_xor_sync(0xffffffffu, sj1, o);
        sj2 += __shfl_xor_sync(0xffffffffu, sj2, o);
        sj3 += __shfl_xor_sync(0xffffffffu, sj3, o);
        tj0 += __shfl_xor_sync(0xffffffffu, tj0, o);
        tj1 += __shfl_xor_sync(0xffffffffu, tj1, o);
        tj2 += __shfl_xor_sync(0xffffffffu, tj2, o);
        tj3 += __shfl_xor_sync(0xffffffffu, tj3, o);
    }

    // sh1/sh2 are dead, stmp aliases them: barrier before reuse
    __syncthreads();

    // ---- Epilogue: e = exp(s); transpose e*fx into stmp (stride 65:
    // bank = (4s + i + col) % 32, conflict-free; node0 col g, node1 col g+33)
    {
        const float ea0 = __expf(sj0), ea1 = __expf(sj1);
        const float ea2 = __expf(sj2), ea3 = __expf(sj3);
        const float eb0 = __expf(tj0), eb1 = __expf(tj1);
        const float eb2 = __expf(tj2), eb3 = __expf(tj3);
        const int col = 4 * s;
        float* st = u.r.stmp;
#pragma unroll
        for (int h = 0; h < 4; h++) {
            const float eh = (h == 0) ? ea0 : (h == 1) ? ea1 : (h == 2) ? ea2 : ea3;
            st[(h * 32 + col + 0) * TSTR + g] = eh * f0;
            st[(h * 32 + col + 1) * TSTR + g] = eh * f1;
            st[(h * 32 + col + 2) * TSTR + g] = eh * f2;
            st[(h * 32 + col + 3) * TSTR + g] = eh * f3;
        }
#pragma unroll
        for (int h = 0; h < 4; h++) {
            const float eh = (h == 0) ? eb0 : (h == 1) ? eb1 : (h == 2) ? eb2 : eb3;
            st[(h * 32 + col + 0) * TSTR + g + 33] = eh * q0;
            st[(h * 32 + col + 1) * TSTR + g + 33] = eh * q1;
            st[(h * 32 + col + 2) * TSTR + g + 33] = eh * q2;
            st[(h * 32 + col + 3) * TSTR + g + 33] = eh * q3;
        }
        if (s == 0) {
            u.r.stz[0 * TSTR + g] = ea0; u.r.stz[0 * TSTR + g + 33] = eb0;
            u.r.stz[1 * TSTR + g] = ea1; u.r.stz[1 * TSTR + g + 33] = eb1;
            u.r.stz[2 * TSTR + g] = ea2; u.r.stz[2 * TSTR + g + 33] = eb2;
            u.r.stz[3 * TSTR + g] = ea3; u.r.stz[3 * TSTR + g + 33] = eb3;
        }
    }
    __syncthreads();

    // ---- block reduction over 64 nodes -> partial row [128 + 4] ----
    if (t < 128) {
        const float* col = u.r.stmp + t * TSTR;
        float a0 = 0.f, a1 = 0.f, a2 = 0.f, a3 = 0.f;
#pragma unroll
        for (int n = 0; n < 32; n += 4) {
            a0 += col[n + 0]; a1 += col[n + 1];
            a2 += col[n + 2]; a3 += col[n + 3];
        }
#pragma unroll
        for (int n = 33; n < 65; n += 4) {
            a0 += col[n + 0]; a1 += col[n + 1];
            a2 += col[n + 2]; a3 += col[n + 3];
        }
        g_part[blockIdx.x * 132 + t] = (a0 + a1) + (a2 + a3);
    } else if (t < 132) {
        const float* col = u.r.stz + (t - 128) * TSTR;
        float a0 = 0.f, a1 = 0.f, a2 = 0.f, a3 = 0.f;
#pragma unroll
        for (int n = 0; n < 32; n += 4) {
            a0 += col[n + 0]; a1 += col[n + 1];
            a2 += col[n + 2]; a3 += col[n + 3];
        }
#pragma unroll
        for (int n = 33; n < 65; n += 4) {
            a0 += col[n + 0]; a1 += col[n + 1];
            a2 += col[n + 2]; a3 += col[n + 3];
        }
        g_part[blockIdx.x * 132 + t] = (a0 + a1) + (a2 + a3);
    }
}

// ---------------------------------------------------------------------------
// Kernel 2 (fused final+broadcast): each block redundantly combines its
// batch's 16 partial rows, normalizes, projects, then writes its 1/32 output
// slice. 256 blocks x 256 threads; batch = blockIdx.x >> 5. Deterministic:
// every block of a batch performs the identical reduction/projection.
// ---------------------------------------------------------------------------
__global__ __launch_bounds__(256) void k_out(
    const float* __restrict__ Ws, const float* __restrict__ bs,
    float4* __restrict__ out)
{
    const int b = blockIdx.x >> 5;       // 32 blocks per batch
    const int t = threadIdx.x;

    __shared__ float sm[128];
    __shared__ float zz[4];
    __shared__ float pr2[128];
    __shared__ __align__(16) float row[32];

    // combine this batch's 16 block-partials for component t
    if (t < 132) {
        const float* p = g_part + (b * 16) * 132 + t;
        float a0 = 0.f, a1 = 0.f, a2 = 0.f, a3 = 0.f;
#pragma unroll
        for (int q = 0; q < 16; q += 4) {
            a0 += p[(q + 0) * 132];
            a1 += p[(q + 1) * 132];
            a2 += p[(q + 2) * 132];
            a3 += p[(q + 3) * 132];
        }
        const float v = (a0 + a1) + (a2 + a3);
        if (t < 128) sm[t] = v;
        else zz[t - 128] = v;
    }
    __syncthreads();
    if (t < 128) sm[t] = sm[t] / zz[t >> 5];
    __syncthreads();

    // projection: o[d] = bs[d] + sum_k sm[k] * Ws[k][d], 4-way k split
    if (t < 128) {
        const int kg = t >> 5, dd = t & 31;
        float a = 0.f;
#pragma unroll
        for (int kk = 0; kk < 32; kk++) {
            const int k = kg * 32 + kk;
            a += sm[k] * __ldg(Ws + k * 32 + dd);
        }
        pr2[t] = a;
    }
    __syncthreads();
    if (t < 32)
        row[t] = __ldg(bs + t) + ((pr2[t] + pr2[t + 32]) + (pr2[t + 64] + pr2[t + 96]));
    __syncthreads();

    // write this block's 256 float4 of the output
    const int gi = blockIdx.x * 256 + t;  // global float4 index
    const int d4 = gi & 7;                // 8 float4 per row
    out[gi] = *(const float4*)(row + d4 * 4);
}

extern "C" void kernel_launch(void* const* d_in, const int* in_sizes, int n_in,
                              void* d_out, int out_size)
{
    const float* x  = (const float*)d_in[0];
    const float* W1 = (const float*)d_in[1];
    const float* b1 = (const float*)d_in[2];
    const float* W2 = (const float*)d_in[3];
    const float* b2 = (const float*)d_in[4];
    const float* W3 = (const float*)d_in[5];
    const float* b3 = (const float*)d_in[6];
    const float* Wa = (const float*)d_in[7];
    // d_in[8] = ba: cancels in the softmax
    const float* Ws = (const float*)d_in[9];
    const float* bs = (const float*)d_in[10];

    k_mlp<<<128, 256>>>(x, W1, b1, W2, b2, W3, b3, Wa);
    k_out<<<256, 256>>>(Ws, bs, (float4*)d_out);
}

// round 11
// speedup vs baseline: 1.2766x; 1.2766x over previous
#include <cuda_runtime.h>

// GATLayer: B=8, N=1024, INP=7, D=32, H=4
// Identity 1: softmax_j(s_i + s_j + ba) == softmax_j(s_j) => att independent
//   of i => output row constant per batch.
// Identity 2: |s_j| small => no max subtraction needed in fp32 softmax:
//   m[b,h,:] = sum_j e^{s_j[h]} fx[j,:] / sum_j e^{s_j[h]}
//   => aggregation = per-block partials computed inside the MLP kernel.

#define BB 8
#define NN 1024
#define DD 32
#define HH 4

// per-block partials: [128 blocks][132] = 128 (e*fx, [h][d]) + 4 (e sums)
__device__ float g_part[128 * 132];

static __device__ __forceinline__ float lrelu(float t) {
    return fmaxf(t, 0.2f * t);
}

// ---------------------------------------------------------------------------
// Kernel 1: message MLP + s_j + per-block softmax-numerator partials.
// 128 blocks x 256 threads; 64 nodes/block, 8 threads per NODE PAIR
// (s = t&7, group g = t>>3 owns nodes g and g+32): every weight LDS.128
// feeds 16 FFMA (2 nodes x 8), h scalars load as float2.
// Accumulators are scalars bound to fixed column groups (A<->2s+rot,
// B<->2s+1-rot, rot=s>>2) so nothing spills; rotation lives only in addresses.
// sh1/sh2 alias the epilogue transpose via a union (barrier separates uses).
// ---------------------------------------------------------------------------
#define HSTR 68
#define TSTR 65

__global__ __launch_bounds__(256) void k_mlp(
    const float* __restrict__ x,
    const float* __restrict__ W1, const float* __restrict__ b1,
    const float* __restrict__ W2, const float* __restrict__ b2,
    const float* __restrict__ W3, const float* __restrict__ b3,
    const float* __restrict__ Wa)
{
    __shared__ float sW1[7 * 64];
    __shared__ float sW2[64 * 64];
    __shared__ float sW3[64 * 32];
    __shared__ float sWaj[32 * 4];       // Wa rows 32..63, [d][h]
    __shared__ float sb1[64], sb2[64], sb3[32];
    __shared__ float sx[448];            // x for this block's 64 nodes
    __shared__ union UU {
        struct { float sh1[64 * HSTR]; float sh2[64 * HSTR]; } a;  // 8704 f
        struct { float stmp[128 * TSTR + TSTR]; float stz[5 * TSTR]; } r;
    } u;

    const int t = threadIdx.x;

    // ---- stage weights + x ----
    {
        float4* d2 = (float4*)sW2; const float4* s2 = (const float4*)W2;
#pragma unroll
        for (int i = 0; i < 4; i++) d2[t + i * 256] = s2[t + i * 256];
        float4* d3 = (float4*)sW3; const float4* s3 = (const float4*)W3;
#pragma unroll
        for (int i = 0; i < 2; i++) d3[t + i * 256] = s3[t + i * 256];
        if (t < 112) {
            ((float4*)sW1)[t] = ((const float4*)W1)[t];
            ((float4*)sx)[t] = ((const float4*)(x + blockIdx.x * 448))[t];
        }
        else if (t < 144) ((float4*)sWaj)[t - 112] = ((const float4*)(Wa + 128))[t - 112];
        else if (t < 160) ((float4*)sb1)[t - 144] = ((const float4*)b1)[t - 144];
        else if (t < 176) ((float4*)sb2)[t - 160] = ((const float4*)b2)[t - 160];
        else if (t < 184) ((float4*)sb3)[t - 176] = ((const float4*)b3)[t - 176];
    }
    __syncthreads();

    const int g = t >> 3;                // node group 0..31 (nodes g, g+32)
    const int s = t & 7;
    const int rot = s >> 2;              // 0/1
    const int cgA = 2 * s + rot;         // accumulator A's column group
    const int cgB = 2 * s + 1 - rot;     // accumulator B's column group

    // ---- Stage A: layer 1 for both nodes ----
    {
        float xv0[7], xv1[7];
#pragma unroll
        for (int k = 0; k < 7; k++) { xv0[k] = sx[g * 7 + k]; xv1[k] = sx[(g + 32) * 7 + k]; }

        const float4 bA = ((const float4*)sb1)[cgA];
        const float4 bB = ((const float4*)sb1)[cgB];
        float nA0 = bA.x, nA1 = bA.y, nA2 = bA.z, nA3 = bA.w;
        float nB0 = bB.x, nB1 = bB.y, nB2 = bB.z, nB3 = bB.w;
        float mA0 = bA.x, mA1 = bA.y, mA2 = bA.z, mA3 = bA.w;
        float mB0 = bB.x, mB1 = bB.y, mB2 = bB.z, mB3 = bB.w;
#pragma unroll
        for (int k = 0; k < 7; k++) {
            const float xk0 = xv0[k], xk1 = xv1[k];
            const float4* row = (const float4*)(sW1 + k * 64);
            const float4 wA = row[cgA];
            const float4 wB = row[cgB];
            nA0 += xk0 * wA.x; nA1 += xk0 * wA.y; nA2 += xk0 * wA.z; nA3 += xk0 * wA.w;
            nB0 += xk0 * wB.x; nB1 += xk0 * wB.y; nB2 += xk0 * wB.z; nB3 += xk0 * wB.w;
            mA0 += xk1 * wA.x; mA1 += xk1 * wA.y; mA2 += xk1 * wA.z; mA3 += xk1 * wA.w;
            mB0 += xk1 * wB.x; mB1 += xk1 * wB.y; mB2 += xk1 * wB.z; mB3 += xk1 * wB.w;
        }
        float4* o0 = (float4*)(u.a.sh1 + g * HSTR + 8 * s);
        float4* o1 = (float4*)(u.a.sh1 + (g + 32) * HSTR + 8 * s);
        o0[rot]     = make_float4(lrelu(nA0), lrelu(nA1), lrelu(nA2), lrelu(nA3));
        o0[1 - rot] = make_float4(lrelu(nB0), lrelu(nB1), lrelu(nB2), lrelu(nB3));
        o1[rot]     = make_float4(lrelu(mA0), lrelu(mA1), lrelu(mA2), lrelu(mA3));
        o1[1 - rot] = make_float4(lrelu(mB0), lrelu(mB1), lrelu(mB2), lrelu(mB3));
    }
    __syncthreads();

    // ---- Stage B: layer 2 for both nodes ----
    {
        const float4 bA = ((const float4*)sb2)[cgA];
        const float4 bB = ((const float4*)sb2)[cgB];
        float nA0 = bA.x, nA1 = bA.y, nA2 = bA.z, nA3 = bA.w;
        float nB0 = bB.x, nB1 = bB.y, nB2 = bB.z, nB3 = bB.w;
        float mA0 = bA.x, mA1 = bA.y, mA2 = bA.z, mA3 = bA.w;
        float mB0 = bB.x, mB1 = bB.y, mB2 = bB.z, mB3 = bB.w;
        const float* h1r0 = u.a.sh1 + g * HSTR;
        const float* h1r1 = u.a.sh1 + (g + 32) * HSTR;
#pragma unroll
        for (int k = 0; k < 64; k += 2) {
            const float2 hk0 = *(const float2*)(h1r0 + k);
            const float2 hk1 = *(const float2*)(h1r1 + k);
            const float4* row0 = (const float4*)(sW2 + k * 64);
            const float4* row1 = (const float4*)(sW2 + (k + 1) * 64);
            {
                const float4 wA = row0[cgA], wB = row0[cgB];
                nA0 += hk0.x * wA.x; nA1 += hk0.x * wA.y; nA2 += hk0.x * wA.z; nA3 += hk0.x * wA.w;
                nB0 += hk0.x * wB.x; nB1 += hk0.x * wB.y; nB2 += hk0.x * wB.z; nB3 += hk0.x * wB.w;
                mA0 += hk1.x * wA.x; mA1 += hk1.x * wA.y; mA2 += hk1.x * wA.z; mA3 += hk1.x * wA.w;
                mB0 += hk1.x * wB.x; mB1 += hk1.x * wB.y; mB2 += hk1.x * wB.z; mB3 += hk1.x * wB.w;
            }
            {
                const float4 wA = row1[cgA], wB = row1[cgB];
                nA0 += hk0.y * wA.x; nA1 += hk0.y * wA.y; nA2 += hk0.y * wA.z; nA3 += hk0.y * wA.w;
                nB0 += hk0.y * wB.x; nB1 += hk0.y * wB.y; nB2 += hk0.y * wB.z; nB3 += hk0.y * wB.w;
                mA0 += hk1.y * wA.x; mA1 += hk1.y * wA.y; mA2 += hk1.y * wA.z; mA3 += hk1.y * wA.w;
                mB0 += hk1.y * wB.x; mB1 += hk1.y * wB.y; mB2 += hk1.y * wB.z; mB3 += hk1.y * wB.w;
            }
        }
        float4* o0 = (float4*)(u.a.sh2 + g * HSTR + 8 * s);
        float4* o1 = (float4*)(u.a.sh2 + (g + 32) * HSTR + 8 * s);
        o0[rot]     = make_float4(lrelu(nA0), lrelu(nA1), lrelu(nA2), lrelu(nA3));
        o0[1 - rot] = make_float4(lrelu(nB0), lrelu(nB1), lrelu(nB2), lrelu(nB3));
        o1[rot]     = make_float4(lrelu(mA0), lrelu(mA1), lrelu(mA2), lrelu(mA3));
        o1[1 - rot] = make_float4(lrelu(mB0), lrelu(mB1), lrelu(mB2), lrelu(mB3));
    }
    __syncthreads();

    // ---- Stage C: layer 3, dims [4s,4s+4) for both nodes ----
    float f0, f1, f2, f3;       // node0 fx
    float q0, q1, q2, q3;       // node1 fx
    {
        const float4 b3v = ((const float4*)sb3)[s];
        float e0 = b3v.x, e1 = b3v.y, e2 = b3v.z, e3 = b3v.w;
        float o0 = 0.f, o1 = 0.f, o2 = 0.f, o3 = 0.f;
        float u0 = b3v.x, u1 = b3v.y, u2 = b3v.z, u3 = b3v.w;
        float v0 = 0.f, v1 = 0.f, v2 = 0.f, v3 = 0.f;
        const float* h2r0 = u.a.sh2 + g * HSTR;
        const float* h2r1 = u.a.sh2 + (g + 32) * HSTR;
#pragma unroll
        for (int j = 0; j < 64; j += 2) {
            const float2 ha = *(const float2*)(h2r0 + j);
            const float2 hb = *(const float2*)(h2r1 + j);
            const float4 w0 = ((const float4*)sW3)[j * 8 + s];
            const float4 w1 = ((const float4*)sW3)[(j + 1) * 8 + s];
            e0 += ha.x * w0.x; e1 += ha.x * w0.y; e2 += ha.x * w0.z; e3 += ha.x * w0.w;
            o0 += ha.y * w1.x; o1 += ha.y * w1.y; o2 += ha.y * w1.z; o3 += ha.y * w1.w;
            u0 += hb.x * w0.x; u1 += hb.x * w0.y; u2 += hb.x * w0.z; u3 += hb.x * w0.w;
            v0 += hb.y * w1.x; v1 += hb.y * w1.y; v2 += hb.y * w1.z; v3 += hb.y * w1.w;
        }
        f0 = e0 + o0; f1 = e1 + o1; f2 = e2 + o2; f3 = e3 + o3;
        q0 = u0 + v0; q1 = u1 + v1; q2 = u2 + v2; q3 = u3 + v3;
    }

    // ---- s_j = fx @ Wa[D:]: partials over lane's 4 dims, 8-lane all-reduce
    float sj0, sj1, sj2, sj3;   // node0
    float tj0, tj1, tj2, tj3;   // node1
    {
        const float4 w0 = ((const float4*)sWaj)[4 * s + 0];
        const float4 w1 = ((const float4*)sWaj)[4 * s + 1];
        const float4 w2 = ((const float4*)sWaj)[4 * s + 2];
        const float4 w3 = ((const float4*)sWaj)[4 * s + 3];
        sj0 = f0 * w0.x + f1 * w1.x + f2 * w2.x + f3 * w3.x;
        sj1 = f0 * w0.y + f1 * w1.y + f2 * w2.y + f3 * w3.y;
        sj2 = f0 * w0.z + f1 * w1.z + f2 * w2.z + f3 * w3.z;
        sj3 = f0 * w0.w + f1 * w1.w + f2 * w2.w + f3 * w3.w;
        tj0 = q0 * w0.x + q1 * w1.x + q2 * w2.x + q3 * w3.x;
        tj1 = q0 * w0.y + q1 * w1.y + q2 * w2.y + q3 * w3.y;
        tj2 = q0 * w0.z + q1 * w1.z + q2 * w2.z + q3 * w3.z;
        tj3 = q0 * w0.w + q1 * w1.w + q2 * w2.w + q3 * w3.w;
    }
#pragma unroll
    for (int o = 1; o < 8; o <<= 1) {
        sj0 += __shfl_xor_sync(0xffffffffu, sj0, o);
        sj1 += __shfl_xor_sync(0xffffffffu, sj1, o);
        sj2 += __shfl_xor_sync(0xffffffffu, sj2, o);
        sj3 += __shfl_xor_sync(0xffffffffu, sj3, o);
        tj0 += __shfl_xor_sync(0xffffffffu, tj0, o);
        tj1 += __shfl_xor_sync(0xffffffffu, tj1, o);
        tj2 += __shfl_xor_sync(0xffffffffu, tj2, o);
        tj3 += __shfl_xor_sync(0xffffffffu, tj3, o);
    }

    // sh1/sh2 are dead, stmp aliases them: barrier before reuse
    __syncthreads();

    // ---- Epilogue: e = exp(s); transpose e*fx into stmp (stride 65:
    // bank = (4s + i + col) % 32, conflict-free; node0 col g, node1 col g+33)
    {
        const float ea0 = __expf(sj0), ea1 = __expf(sj1);
        const float ea2 = __expf(sj2), ea3 = __expf(sj3);
        const float eb0 = __expf(tj0), eb1 = __expf(tj1);
        const float eb2 = __expf(tj2), eb3 = __expf(tj3);
        const int col = 4 * s;
        float* st = u.r.stmp;
#pragma unroll
        for (int h = 0; h < 4; h++) {
            const float eh = (h == 0) ? ea0 : (h == 1) ? ea1 : (h == 2) ? ea2 : ea3;
            st[(h * 32 + col + 0) * TSTR + g] = eh * f0;
            st[(h * 32 + col + 1) * TSTR + g] = eh * f1;
            st[(h * 32 + col + 2) * TSTR + g] = eh * f2;
            st[(h * 32 + col + 3) * TSTR + g] = eh * f3;
        }
#pragma unroll
        for (int h = 0; h < 4; h++) {
            const float eh = (h == 0) ? eb0 : (h == 1) ? eb1 : (h == 2) ? eb2 : eb3;
            st[(h * 32 + col + 0) * TSTR + g + 33] = eh * q0;
            st[(h * 32 + col + 1) * TSTR + g + 33] = eh * q1;
            st[(h * 32 + col + 2) * TSTR + g + 33] = eh * q2;
            st[(h * 32 + col + 3) * TSTR + g + 33] = eh * q3;
        }
        if (s == 0) {
            u.r.stz[0 * TSTR + g] = ea0; u.r.stz[0 * TSTR + g + 33] = eb0;
            u.r.stz[1 * TSTR + g] = ea1; u.r.stz[1 * TSTR + g + 33] = eb1;
            u.r.stz[2 * TSTR + g] = ea2; u.r.stz[2 * TSTR + g + 33] = eb2;
            u.r.stz[3 * TSTR + g] = ea3; u.r.stz[3 * TSTR + g + 33] = eb3;
        }
    }
    __syncthreads();

    // ---- block reduction over 64 nodes -> partial row [128 + 4] ----
    if (t < 128) {
        const float* col = u.r.stmp + t * TSTR;
        float a0 = 0.f, a1 = 0.f, a2 = 0.f, a3 = 0.f;
#pragma unroll
        for (int n = 0; n < 32; n += 4) {
            a0 += col[n + 0]; a1 += col[n + 1];
            a2 += col[n + 2]; a3 += col[n + 3];
        }
#pragma unroll
        for (int n = 33; n < 65; n += 4) {
            a0 += col[n + 0]; a1 += col[n + 1];
            a2 += col[n + 2]; a3 += col[n + 3];
        }
        g_part[blockIdx.x * 132 + t] = (a0 + a1) + (a2 + a3);
    } else if (t < 132) {
        const float* col = u.r.stz + (t - 128) * TSTR;
        float a0 = 0.f, a1 = 0.f, a2 = 0.f, a3 = 0.f;
#pragma unroll
        for (int n = 0; n < 32; n += 4) {
            a0 += col[n + 0]; a1 += col[n + 1];
            a2 += col[n + 2]; a3 += col[n + 3];
        }
#pragma unroll
        for (int n = 33; n < 65; n += 4) {
            a0 += col[n + 0]; a1 += col[n + 1];
            a2 += col[n + 2]; a3 += col[n + 3];
        }
        g_part[blockIdx.x * 132 + t] = (a0 + a1) + (a2 + a3);
    }
}

// ---------------------------------------------------------------------------
// Kernel 2: per-batch combine + projection + full output write.
// 8 blocks x 1024 threads (one block per batch). The 16-partial reduction
// and projection run once per batch (threads < 132 / < 128); then all 1024
// threads write the batch's 1024 rows with coalesced stores
// (out[b*8192 + j*1024 + t] = row4[t&7] — 512B contiguous per warp-store).
// ---------------------------------------------------------------------------
__global__ __launch_bounds__(1024) void k_fin(
    const float* __restrict__ Ws, const float* __restrict__ bs,
    float4* __restrict__ out)
{
    const int b = blockIdx.x;
    const int t = threadIdx.x;

    __shared__ float sm[128];
    __shared__ float zz[4];
    __shared__ float pr2[128];
    __shared__ __align__(16) float row[32];

    // combine this batch's 16 block-partials for component t
    if (t < 132) {
        const float* p = g_part + (b * 16) * 132 + t;
        float a0 = 0.f, a1 = 0.f, a2 = 0.f, a3 = 0.f;
#pragma unroll
        for (int q = 0; q < 16; q += 4) {
            a0 += p[(q + 0) * 132];
            a1 += p[(q + 1) * 132];
            a2 += p[(q + 2) * 132];
            a3 += p[(q + 3) * 132];
        }
        const float v = (a0 + a1) + (a2 + a3);
        if (t < 128) sm[t] = v;
        else zz[t - 128] = v;
    }
    __syncthreads();
    if (t < 128) sm[t] = sm[t] / zz[t >> 5];
    __syncthreads();

    // projection: o[d] = bs[d] + sum_k sm[k] * Ws[k][d], 4-way k split
    if (t < 128) {
        const int kg = t >> 5, dd = t & 31;
        float a = 0.f;
#pragma unroll
        for (int kk = 0; kk < 32; kk++) {
            const int k = kg * 32 + kk;
            a += sm[k] * __ldg(Ws + k * 32 + dd);
        }
        pr2[t] = a;
    }
    __syncthreads();
    if (t < 32)
        row[t] = __ldg(bs + t) + ((pr2[t] + pr2[t + 32]) + (pr2[t + 64] + pr2[t + 96]));
    __syncthreads();

    // write the batch's 8192 float4 (1 MB / 8): thread t stores row4[t&7]
    // at out[b*8192 + j*1024 + t], j = 0..7 — fully coalesced.
    const float4 v = *(const float4*)(row + (t & 7) * 4);
    float4* ob = out + b * 8192 + t;
#pragma unroll
    for (int j = 0; j < 8; j++) ob[j * 1024] = v;
}

extern "C" void kernel_launch(void* const* d_in, const int* in_sizes, int n_in,
                              void* d_out, int out_size)
{
    const float* x  = (const float*)d_in[0];
    const float* W1 = (const float*)d_in[1];
    const float* b1 = (const float*)d_in[2];
    const float* W2 = (const float*)d_in[3];
    const float* b2 = (const float*)d_in[4];
    const float* W3 = (const float*)d_in[5];
    const float* b3 = (const float*)d_in[6];
    const float* Wa = (const float*)d_in[7];
    // d_in[8] = ba: cancels in the softmax
    const float* Ws = (const float*)d_in[9];
    const float* bs = (const float*)d_in[10];

    k_mlp<<<128, 256>>>(x, W1, b1, W2, b2, W3, b3, Wa);
    k_fin<<<8, 1024>>>(Ws, bs, (float4*)d_out);
}